// round 9
// baseline (speedup 1.0000x reference)
#include <cuda_runtime.h>
#include <cstdint>

#define TPB 512

#define NBATCH 2048
#define CDIM 192
#define NPOS 64
#define NHEAD 6
#define NGRP 3
#define NS 16

#define RSX 68     // row stride for x / attn-out tile [192][64]
#define RSQ 68     // row stride for q tile [192][64]
#define RTW 192    // row stride, transposed weight half [96 k][192 co]
#define RSS 16     // row stride for samp/k/v tiles [192][16]

// shared-memory layout (float offsets)
#define O_XS    0          // 13056 (x; later attn-out)
#define O_QS    13056      // 13056
#define O_WT    26112      // UNION: weight K-half (96*192 = 18432)  OR  samp/k/v
#define O_SAMP  (O_WT)             // 3072
#define O_KS    (O_WT + 3072)      // 3072
#define O_VS    (O_WT + 6144)      // 3072
// persistent tail (never aliased by WT)
#define O_RPE   50688      // 1350
#define O_DWW   52038      // 576
#define O_DWB   52614      // 64
#define O_LNG   52678      // 64
#define O_LNB   52742      // 64
#define O_PWW   52806      // 128
#define O_POS   52934      // 96
#define O_SMPW  53030      // 192
#define O_SMPI  53222      // 192 (ints)
#define SMEMF   53414
#define SMEM_BYTES (SMEMF * 4)   // 213656 B

#define Y_SIZE   (NBATCH * CDIM * NPOS)
#define PR_SIZE  (NBATCH * NGRP * NS * 2)
#define POS_OFF  Y_SIZE
#define REF_OFF  (Y_SIZE + PR_SIZE)

// ---- weight K-half staging: all 192 co rows, 96 k cols, stored transposed WT[k][co] ----
// 18432 floats = 4608 float4 quads; thread handles quads q = tid + j*512, j=0..8.
// quad q -> co = q/24, kq = q%24 (24 quads of k per co row).
__device__ __forceinline__ void ldg_pass(const float* __restrict__ W, int k0,
                                         int tid, float4 r[9])
{
#pragma unroll
    for (int j = 0; j < 9; ++j) {
        int q = tid + j * 512;
        int co = q / 24;
        int kq = q - co * 24;
        r[j] = __ldg((const float4*)&W[co * 192 + k0 + kq * 4]);
    }
}

__device__ __forceinline__ void sts_pass(float* __restrict__ sm, int tid, const float4 r[9])
{
#pragma unroll
    for (int j = 0; j < 9; ++j) {
        int q = tid + j * 512;
        int co = q / 24;
        int kq = q - co * 24;
        int kb = kq * 4;
        sm[O_WT + (kb + 0) * RTW + co] = r[j].x;
        sm[O_WT + (kb + 1) * RTW + co] = r[j].y;
        sm[O_WT + (kb + 2) * RTW + co] = r[j].z;
        sm[O_WT + (kb + 3) * RTW + co] = r[j].w;
    }
}

// 192x64 GEMM, K=192: out[co][p] = bias[co] + sum_k W[co][k] * in[k][p]
// Two K-halves (96 each) over ALL 192 co; accumulators persist across halves.
// Thread tile: 6 co x 4 p (24 outputs). wregA holds K-half 0 on entry.
template <bool TO_SMEM>
__device__ __forceinline__ void gemm_big(const float* __restrict__ W, const float* __restrict__ bias,
                                         int inOff, float* __restrict__ gout,
                                         float* __restrict__ sm, int tid, float4 wregA[9])
{
    const int warp = tid >> 5, lane = tid & 31;
    const int p = ((warp >> 2) * 4 + (lane & 3)) * 4;     // 16 p-quads
    const int cb = (warp & 3) * 8 + (lane >> 2);          // 32 co-blocks
    const int col = cb * 6;                               // 0..186

    float4 acc[6];
#pragma unroll
    for (int i = 0; i < 6; ++i) {
        float bi = bias[col + i];
        acc[i] = make_float4(bi, bi, bi, bi);
    }

    // ---- K-half 0 ----
    sts_pass(sm, tid, wregA);
    __syncthreads();
    float4 wregB[9];
    ldg_pass(W, 96, tid, wregB);      // overlap with half-0 compute
#pragma unroll 2
    for (int k = 0; k < 96; ++k) {
        const float* wrow = &sm[O_WT + k * RTW + col];
        float2 w01 = *(const float2*)&wrow[0];
        float2 w23 = *(const float2*)&wrow[2];
        float2 w45 = *(const float2*)&wrow[4];
        float4 xv = *(const float4*)&sm[inOff + k * RSX + p];
        acc[0].x += w01.x * xv.x; acc[0].y += w01.x * xv.y; acc[0].z += w01.x * xv.z; acc[0].w += w01.x * xv.w;
        acc[1].x += w01.y * xv.x; acc[1].y += w01.y * xv.y; acc[1].z += w01.y * xv.z; acc[1].w += w01.y * xv.w;
        acc[2].x += w23.x * xv.x; acc[2].y += w23.x * xv.y; acc[2].z += w23.x * xv.z; acc[2].w += w23.x * xv.w;
        acc[3].x += w23.y * xv.x; acc[3].y += w23.y * xv.y; acc[3].z += w23.y * xv.z; acc[3].w += w23.y * xv.w;
        acc[4].x += w45.x * xv.x; acc[4].y += w45.x * xv.y; acc[4].z += w45.x * xv.z; acc[4].w += w45.x * xv.w;
        acc[5].x += w45.y * xv.x; acc[5].y += w45.y * xv.y; acc[5].z += w45.y * xv.z; acc[5].w += w45.y * xv.w;
    }
    __syncthreads();                  // all readers done with half-0 WT

    // ---- K-half 1 ----
    sts_pass(sm, tid, wregB);
    __syncthreads();
#pragma unroll 2
    for (int k = 0; k < 96; ++k) {
        const float* wrow = &sm[O_WT + k * RTW + col];
        float2 w01 = *(const float2*)&wrow[0];
        float2 w23 = *(const float2*)&wrow[2];
        float2 w45 = *(const float2*)&wrow[4];
        float4 xv = *(const float4*)&sm[inOff + (96 + k) * RSX + p];
        acc[0].x += w01.x * xv.x; acc[0].y += w01.x * xv.y; acc[0].z += w01.x * xv.z; acc[0].w += w01.x * xv.w;
        acc[1].x += w01.y * xv.x; acc[1].y += w01.y * xv.y; acc[1].z += w01.y * xv.z; acc[1].w += w01.y * xv.w;
        acc[2].x += w23.x * xv.x; acc[2].y += w23.x * xv.y; acc[2].z += w23.x * xv.z; acc[2].w += w23.x * xv.w;
        acc[3].x += w23.y * xv.x; acc[3].y += w23.y * xv.y; acc[3].z += w23.y * xv.z; acc[3].w += w23.y * xv.w;
        acc[4].x += w45.x * xv.x; acc[4].y += w45.x * xv.y; acc[4].z += w45.x * xv.z; acc[4].w += w45.x * xv.w;
        acc[5].x += w45.y * xv.x; acc[5].y += w45.y * xv.y; acc[5].z += w45.y * xv.z; acc[5].w += w45.y * xv.w;
    }
#pragma unroll
    for (int i = 0; i < 6; ++i) {
        if (TO_SMEM) *(float4*)&sm[O_QS + (col + i) * RSQ + p] = acc[i];
        else         *(float4*)&gout[(col + i) * 64 + p] = acc[i];
    }
    __syncthreads();
}

__global__ void __launch_bounds__(TPB, 1)
dat_fused_kernel(const float* __restrict__ x,
                 const float* __restrict__ wq, const float* __restrict__ bq,
                 const float* __restrict__ wk, const float* __restrict__ bk,
                 const float* __restrict__ wv, const float* __restrict__ bv,
                 const float* __restrict__ wo, const float* __restrict__ bo,
                 const float* __restrict__ dww, const float* __restrict__ dwb,
                 const float* __restrict__ lng, const float* __restrict__ lnb,
                 const float* __restrict__ pww, const float* __restrict__ rpe,
                 float* __restrict__ out, int writePR)
{
    extern __shared__ float sm[];
    const int b = blockIdx.x;
    const int tid = threadIdx.x;

    // prefetch q-proj K-half 0 while staging x
    float4 wreg[9];
    ldg_pass(wq, 0, tid, wreg);

    // ---- stage x (transpose to [c][p]) and persistent params ----
    const float* xb = x + (size_t)b * (NPOS * CDIM);
    for (int t = tid; t < NPOS * CDIM; t += TPB) {
        int p = t / CDIM;
        int c = t - p * CDIM;
        sm[O_XS + c * RSX + p] = xb[t];
    }
    for (int t = tid; t < 1350; t += TPB) sm[O_RPE + t] = rpe[t];
    for (int t = tid; t < 576; t += TPB) sm[O_DWW + t] = dww[t];
    if (tid < 64) {
        sm[O_DWB + tid] = dwb[tid];
        sm[O_LNG + tid] = lng[tid];
        sm[O_LNB + tid] = lnb[tid];
    }
    if (tid >= 64 && tid < 192) sm[O_PWW + tid - 64] = pww[tid - 64];
    __syncthreads();

    // ---- q = Wq x + bq ----
    gemm_big<true>(wq, bq, O_XS, nullptr, sm, tid, wreg);

    // ---- offset network: 48 items (group g, sample s), 3 per warp ----
    const int warp = tid >> 5, lane = tid & 31;
    for (int kk = 0; kk < 3; ++kk) {
        const int item = warp * 3 + kk;
        const int g = item >> 4;
        const int s = item & 15;
        const int si = s >> 2, sj = s & 3;
        const int ch0 = lane, ch1 = lane + 32;
        float v0 = sm[O_DWB + ch0];
        float v1 = sm[O_DWB + ch1];
        const int iy0 = 2 * si - 1, ix0 = 2 * sj - 1;
#pragma unroll
        for (int di = 0; di < 3; ++di) {
            int iy = iy0 + di;
            if (iy < 0 || iy > 7) continue;
#pragma unroll
            for (int dj = 0; dj < 3; ++dj) {
                int ix = ix0 + dj;
                if (ix < 0 || ix > 7) continue;
                float q0 = sm[O_QS + (g * 64 + ch0) * RSQ + iy * 8 + ix];
                float q1 = sm[O_QS + (g * 64 + ch1) * RSQ + iy * 8 + ix];
                v0 += sm[O_DWW + ch0 * 9 + di * 3 + dj] * q0;
                v1 += sm[O_DWW + ch1 * 9 + di * 3 + dj] * q1;
            }
        }
        float ssum = v0 + v1, ssq = v0 * v0 + v1 * v1;
#pragma unroll
        for (int o = 16; o > 0; o >>= 1) {
            ssum += __shfl_xor_sync(0xffffffffu, ssum, o);
            ssq += __shfl_xor_sync(0xffffffffu, ssq, o);
        }
        float mu = ssum * (1.0f / 64.0f);
        float var = ssq * (1.0f / 64.0f) - mu * mu;
        float rstd = rsqrtf(var + 1e-5f);
        v0 = (v0 - mu) * rstd * sm[O_LNG + ch0] + sm[O_LNB + ch0];
        v1 = (v1 - mu) * rstd * sm[O_LNG + ch1] + sm[O_LNB + ch1];
        v0 = 0.5f * v0 * (1.0f + erff(v0 * 0.70710678118654752f));
        v1 = 0.5f * v1 * (1.0f + erff(v1 * 0.70710678118654752f));
        float o0 = sm[O_PWW + ch0] * v0 + sm[O_PWW + ch1] * v1;
        float o1 = sm[O_PWW + 64 + ch0] * v0 + sm[O_PWW + 64 + ch1] * v1;
#pragma unroll
        for (int o = 16; o > 0; o >>= 1) {
            o0 += __shfl_xor_sync(0xffffffffu, o0, o);
            o1 += __shfl_xor_sync(0xffffffffu, o1, o);
        }
        if (lane == 0) {
            float offy = tanhf(o0) * (2.0f / 3.0f);
            float offx = tanhf(o1) * (2.0f / 3.0f);
            float ry = (2 * si - 3) * 0.25f;
            float rx = (2 * sj - 3) * 0.25f;
            float py = offy + ry;
            float px = offx + rx;
            sm[O_POS + item * 2 + 0] = py;
            sm[O_POS + item * 2 + 1] = px;
            float gx = (px + 1.0f) * 3.5f;
            float gy = (py + 1.0f) * 3.5f;
            float x0f = floorf(gx), y0f = floorf(gy);
            int jx0 = (int)x0f, jy0 = (int)y0f;
            float wx1 = gx - x0f, wy1 = gy - y0f;
            float wxs[2] = {1.0f - wx1, wx1};
            float wys[2] = {1.0f - wy1, wy1};
            int* smpI = (int*)sm;
#pragma unroll
            for (int n = 0; n < 4; ++n) {
                int xi = jx0 + (n & 1);
                int yi = jy0 + (n >> 1);
                bool val = (xi >= 0 && xi <= 7 && yi >= 0 && yi <= 7);
                sm[O_SMPW + item * 4 + n] = val ? wxs[n & 1] * wys[n >> 1] : 0.0f;
                smpI[O_SMPI + item * 4 + n] = val ? (yi * 8 + xi) : 0;
            }
            if (writePR) {
                size_t po = ((size_t)b * 48 + item) * 2;
                out[POS_OFF + po + 0] = py;
                out[POS_OFF + po + 1] = px;
                out[REF_OFF + po + 0] = ry;
                out[REF_OFF + po + 1] = rx;
            }
        }
    }
    __syncthreads();

    // ---- bilinear sample x at pos -> samp[c][s] ----
    for (int t = tid; t < CDIM * NS; t += TPB) {
        int c = t >> 4;
        int s = t & 15;
        int item = (c >> 6) * 16 + s;
        const float* wp = &sm[O_SMPW + item * 4];
        const int* ip = ((const int*)sm) + O_SMPI + item * 4;
        const float* row = &sm[O_XS + c * RSX];
        sm[O_SAMP + c * RSS + s] =
            wp[0] * row[ip[0]] + wp[1] * row[ip[1]] + wp[2] * row[ip[2]] + wp[3] * row[ip[3]];
    }
    __syncthreads();

    // ---- k, v projections: weights direct from L2, thread = (co, 8 s-cols) ----
    if (tid < 384) {
        const int co = tid >> 1;
        const int sh = (tid & 1) * 8;
        const float bkc = bk[co], bvc = bv[co];
        float4 ak0 = make_float4(bkc, bkc, bkc, bkc), ak1 = ak0;
        float4 av0 = make_float4(bvc, bvc, bvc, bvc), av1 = av0;
#pragma unroll 4
        for (int k4 = 0; k4 < 48; ++k4) {
            float4 wk4 = __ldg((const float4*)&wk[co * 192 + k4 * 4]);
            float4 wv4 = __ldg((const float4*)&wv[co * 192 + k4 * 4]);
#pragma unroll
            for (int j = 0; j < 4; ++j) {
                float wkj = (j == 0) ? wk4.x : (j == 1) ? wk4.y : (j == 2) ? wk4.z : wk4.w;
                float wvj = (j == 0) ? wv4.x : (j == 1) ? wv4.y : (j == 2) ? wv4.z : wv4.w;
                float4 s0 = *(const float4*)&sm[O_SAMP + (k4 * 4 + j) * RSS + sh];
                float4 s1 = *(const float4*)&sm[O_SAMP + (k4 * 4 + j) * RSS + sh + 4];
                ak0.x += wkj * s0.x; ak0.y += wkj * s0.y; ak0.z += wkj * s0.z; ak0.w += wkj * s0.w;
                ak1.x += wkj * s1.x; ak1.y += wkj * s1.y; ak1.z += wkj * s1.z; ak1.w += wkj * s1.w;
                av0.x += wvj * s0.x; av0.y += wvj * s0.y; av0.z += wvj * s0.z; av0.w += wvj * s0.w;
                av1.x += wvj * s1.x; av1.y += wvj * s1.y; av1.z += wvj * s1.z; av1.w += wvj * s1.w;
            }
        }
        *(float4*)&sm[O_KS + co * RSS + sh] = ak0;
        *(float4*)&sm[O_KS + co * RSS + sh + 4] = ak1;
        *(float4*)&sm[O_VS + co * RSS + sh] = av0;
        *(float4*)&sm[O_VS + co * RSS + sh + 4] = av1;
    }
    __syncthreads();

    // ---- attention: item = (head, query position), 384 items ----
    for (int it = tid; it < NHEAD * NPOS; it += TPB) {
        const int h = it >> 6;
        const int p = it & 63;
        const int g = h >> 1;
        float a[16];
#pragma unroll
        for (int s = 0; s < 16; ++s) a[s] = 0.0f;
#pragma unroll 4
        for (int c = 0; c < 32; ++c) {
            float qv = sm[O_QS + (h * 32 + c) * RSQ + p];
            const float4* kr = (const float4*)&sm[O_KS + (h * 32 + c) * RSS];
            float4 k0 = kr[0], k1 = kr[1], k2 = kr[2], k3 = kr[3];
            a[0] += qv * k0.x; a[1] += qv * k0.y; a[2] += qv * k0.z; a[3] += qv * k0.w;
            a[4] += qv * k1.x; a[5] += qv * k1.y; a[6] += qv * k1.z; a[7] += qv * k1.w;
            a[8] += qv * k2.x; a[9] += qv * k2.y; a[10] += qv * k2.z; a[11] += qv * k2.w;
            a[12] += qv * k3.x; a[13] += qv * k3.y; a[14] += qv * k3.z; a[15] += qv * k3.w;
        }
        const float scale = 0.17677669529663687f;
        float qy = (2 * (p >> 3) - 7) * 0.125f;
        float qx = (2 * (p & 7) - 7) * 0.125f;
        const float* rpeh = &sm[O_RPE + h * 225];
        float mx = -1e30f;
#pragma unroll
        for (int s = 0; s < 16; ++s) {
            float py = sm[O_POS + (g * 16 + s) * 2 + 0];
            float px = sm[O_POS + (g * 16 + s) * 2 + 1];
            float dy = (qy - py) * 0.5f;
            float dx = (qx - px) * 0.5f;
            float gx = (dx + 1.0f) * 7.0f;
            float gy = (dy + 1.0f) * 7.0f;
            float x0f = floorf(gx), y0f = floorf(gy);
            int jx0 = (int)x0f, jy0 = (int)y0f;
            float wx1 = gx - x0f, wy1 = gy - y0f;
            float bias = 0.0f;
            if (jx0 >= 0 && jx0 <= 14 && jy0 >= 0 && jy0 <= 14)
                bias += (1.0f - wx1) * (1.0f - wy1) * rpeh[jy0 * 15 + jx0];
            if (jx0 + 1 >= 0 && jx0 + 1 <= 14 && jy0 >= 0 && jy0 <= 14)
                bias += wx1 * (1.0f - wy1) * rpeh[jy0 * 15 + jx0 + 1];
            if (jx0 >= 0 && jx0 <= 14 && jy0 + 1 >= 0 && jy0 + 1 <= 14)
                bias += (1.0f - wx1) * wy1 * rpeh[(jy0 + 1) * 15 + jx0];
            if (jx0 + 1 >= 0 && jx0 + 1 <= 14 && jy0 + 1 >= 0 && jy0 + 1 <= 14)
                bias += wx1 * wy1 * rpeh[(jy0 + 1) * 15 + jx0 + 1];
            a[s] = a[s] * scale + bias;
            mx = fmaxf(mx, a[s]);
        }
        float ssum = 0.0f;
#pragma unroll
        for (int s = 0; s < 16; ++s) { a[s] = __expf(a[s] - mx); ssum += a[s]; }
        float inv = 1.0f / ssum;
#pragma unroll
        for (int s = 0; s < 16; ++s) a[s] *= inv;
#pragma unroll 4
        for (int cl = 0; cl < 32; ++cl) {
            int c = h * 32 + cl;
            const float4* vr = (const float4*)&sm[O_VS + c * RSS];
            float4 v0 = vr[0], v1 = vr[1], v2 = vr[2], v3 = vr[3];
            float acc = a[0]*v0.x + a[1]*v0.y + a[2]*v0.z + a[3]*v0.w
                      + a[4]*v1.x + a[5]*v1.y + a[6]*v1.z + a[7]*v1.w
                      + a[8]*v2.x + a[9]*v2.y + a[10]*v2.z + a[11]*v2.w
                      + a[12]*v3.x + a[13]*v3.y + a[14]*v3.z + a[15]*v3.w;
            sm[O_XS + c * RSX + p] = acc;
        }
    }

    // prefetch o-proj K-half 0 (overlaps the sync/tail of attention)
    ldg_pass(wo, 0, tid, wreg);
    __syncthreads();

    // ---- y = Wo out + bo (direct to gmem) ----
    gemm_big<false>(wo, bo, O_XS, out + (size_t)b * (CDIM * NPOS), sm, tid, wreg);
}

extern "C" void kernel_launch(void* const* d_in, const int* in_sizes, int n_in,
                              void* d_out, int out_size)
{
    (void)in_sizes; (void)n_in;
    const float* x   = (const float*)d_in[0];
    const float* wq  = (const float*)d_in[1];
    const float* bq  = (const float*)d_in[2];
    const float* wk  = (const float*)d_in[3];
    const float* bk  = (const float*)d_in[4];
    const float* wv  = (const float*)d_in[5];
    const float* bv  = (const float*)d_in[6];
    const float* wo  = (const float*)d_in[7];
    const float* bo  = (const float*)d_in[8];
    const float* dww = (const float*)d_in[9];
    const float* dwb = (const float*)d_in[10];
    const float* lng = (const float*)d_in[11];
    const float* lnb = (const float*)d_in[12];
    const float* pww = (const float*)d_in[13];
    const float* rpe = (const float*)d_in[14];
    float* out = (float*)d_out;

    int writePR = (out_size >= (REF_OFF + PR_SIZE)) ? 1 : 0;

    cudaFuncSetAttribute(dat_fused_kernel,
                         cudaFuncAttributeMaxDynamicSharedMemorySize, SMEM_BYTES);
    dat_fused_kernel<<<NBATCH, TPB, SMEM_BYTES>>>(
        x, wq, bq, wk, bk, wv, bv, wo, bo, dww, dwb, lng, lnb, pww, rpe, out, writePR);
}

// round 10
// speedup vs baseline: 1.4236x; 1.4236x over previous
#include <cuda_runtime.h>
#include <cstdint>

#define TPB 512

#define NBATCH 2048
#define CDIM 192
#define NPOS 64
#define NHEAD 6
#define NGRP 3
#define NS 16

#define RSX 68     // row stride for x / attn-out tile [192][64]
#define RSQ 68     // row stride for q tile [192][64]
#define RSW 68     // row stride for weight pass buffer [192 co][64 k] (+4 pad, 16B-aligned)
#define RSS 16     // row stride for samp/k/v tiles [192][16]
#define WBUF 13056 // floats per weight pass buffer (192*68)

// shared-memory layout (float offsets)
#define O_XS    0          // 13056 (x; later attn-out)
#define O_QS    13056      // 13056
#define O_WT    26112      // UNION: 2 weight pass buffers (2*13056)  OR  samp/k/v
#define O_SAMP  (O_WT)             // 3072 (buffer0 region)
#define O_KS    (O_WT + 3072)      // 3072
#define O_VS    (O_WT + 6144)      // 3072
// persistent tail (never aliased by WT)
#define O_RPE   52224      // 1350
#define O_DWW   53574      // 576
#define O_DWB   54150      // 64
#define O_LNG   54214      // 64
#define O_LNB   54278      // 64
#define O_PWW   54342      // 128
#define O_POS   54470      // 96
#define O_SMPW  54566      // 192
#define O_SMPI  54758      // 192 (ints)
#define SMEMF   54950
#define SMEM_BYTES (SMEMF * 4)   // 219800 B

#define Y_SIZE   (NBATCH * CDIM * NPOS)
#define PR_SIZE  (NBATCH * NGRP * NS * 2)
#define POS_OFF  Y_SIZE
#define REF_OFF  (Y_SIZE + PR_SIZE)

#define FMA4(A, s, X) { (A).x += (s)*(X).x; (A).y += (s)*(X).y; (A).z += (s)*(X).z; (A).w += (s)*(X).w; }

// ---- async-stage one 64-k pass of weights: W[192 co][k0..k0+63] -> smem[co*68 + kc*4] ----
// 3072 float4 chunks; thread handles q = tid + j*512, j=0..5; chunk q -> co=q>>4, kc=q&15.
__device__ __forceinline__ void cp_stage(const float* __restrict__ W, int k0,
                                         uint32_t dstBase, int tid)
{
#pragma unroll
    for (int j = 0; j < 6; ++j) {
        int q = tid + j * 512;
        int co = q >> 4;
        int kc = q & 15;
        uint32_t dst = dstBase + (uint32_t)(co * RSW + kc * 4) * 4u;
        const float* src = W + co * 192 + k0 + kc * 4;
        asm volatile("cp.async.cg.shared.global [%0], [%1], 16;" :: "r"(dst), "l"(src));
    }
    asm volatile("cp.async.commit_group;" ::: "memory");
}

// 192x64 GEMM, K=192: out[co][p] = bias[co] + sum_k W[co][k] * in[k][p]
// 3 K-passes of 64, weights double-buffered via cp.async; accumulators persist.
// Thread tile: 6 co x 4 p. Pass p uses buffer (p+1)&1; caller pre-issued pass 0 into buffer 1.
template <bool TO_SMEM>
__device__ __forceinline__ void gemm_big(const float* __restrict__ W, const float* __restrict__ bias,
                                         int inOff, float* __restrict__ gout,
                                         float* __restrict__ sm, uint32_t sb, int tid)
{
    const int warp = tid >> 5, lane = tid & 31;
    const int p = ((warp >> 2) * 4 + (lane & 3)) * 4;       // 16 p-quads
    const int col = ((warp & 3) * 8 + (lane >> 2)) * 6;     // 0..186

    float4 acc[6];
#pragma unroll
    for (int i = 0; i < 6; ++i) {
        float bi = bias[col + i];
        acc[i] = make_float4(bi, bi, bi, bi);
    }

#pragma unroll 1
    for (int pass = 0; pass < 3; ++pass) {
        if (pass < 2) {
            // stage pass+1 into buffer (pass&1); that buffer's last readers
            // (compute pass-1) finished before the trailing sync below.
            cp_stage(W, (pass + 1) * 64, sb + (uint32_t)(O_WT + (pass & 1) * WBUF) * 4u, tid);
            asm volatile("cp.async.wait_group 1;" ::: "memory");
        } else {
            asm volatile("cp.async.wait_group 0;" ::: "memory");
        }
        __syncthreads();
        const int wb = O_WT + ((pass + 1) & 1) * WBUF;
        const int kb = pass * 64;
#pragma unroll 2
        for (int k4 = 0; k4 < 16; ++k4) {
            float4 w0 = *(const float4*)&sm[wb + (col + 0) * RSW + k4 * 4];
            float4 w1 = *(const float4*)&sm[wb + (col + 1) * RSW + k4 * 4];
            float4 w2 = *(const float4*)&sm[wb + (col + 2) * RSW + k4 * 4];
            float4 w3 = *(const float4*)&sm[wb + (col + 3) * RSW + k4 * 4];
            float4 w4 = *(const float4*)&sm[wb + (col + 4) * RSW + k4 * 4];
            float4 w5 = *(const float4*)&sm[wb + (col + 5) * RSW + k4 * 4];
            float4 x0 = *(const float4*)&sm[inOff + (kb + k4 * 4 + 0) * RSX + p];
            float4 x1 = *(const float4*)&sm[inOff + (kb + k4 * 4 + 1) * RSX + p];
            float4 x2 = *(const float4*)&sm[inOff + (kb + k4 * 4 + 2) * RSX + p];
            float4 x3 = *(const float4*)&sm[inOff + (kb + k4 * 4 + 3) * RSX + p];
            FMA4(acc[0], w0.x, x0); FMA4(acc[0], w0.y, x1); FMA4(acc[0], w0.z, x2); FMA4(acc[0], w0.w, x3);
            FMA4(acc[1], w1.x, x0); FMA4(acc[1], w1.y, x1); FMA4(acc[1], w1.z, x2); FMA4(acc[1], w1.w, x3);
            FMA4(acc[2], w2.x, x0); FMA4(acc[2], w2.y, x1); FMA4(acc[2], w2.z, x2); FMA4(acc[2], w2.w, x3);
            FMA4(acc[3], w3.x, x0); FMA4(acc[3], w3.y, x1); FMA4(acc[3], w3.z, x2); FMA4(acc[3], w3.w, x3);
            FMA4(acc[4], w4.x, x0); FMA4(acc[4], w4.y, x1); FMA4(acc[4], w4.z, x2); FMA4(acc[4], w4.w, x3);
            FMA4(acc[5], w5.x, x0); FMA4(acc[5], w5.y, x1); FMA4(acc[5], w5.z, x2); FMA4(acc[5], w5.w, x3);
        }
        __syncthreads();   // buffer free for the next pass's cp.async
    }

#pragma unroll
    for (int i = 0; i < 6; ++i) {
        if (TO_SMEM) *(float4*)&sm[O_QS + (col + i) * RSQ + p] = acc[i];
        else         *(float4*)&gout[(col + i) * 64 + p] = acc[i];
    }
    __syncthreads();
}

__global__ void __launch_bounds__(TPB, 1)
dat_fused_kernel(const float* __restrict__ x,
                 const float* __restrict__ wq, const float* __restrict__ bq,
                 const float* __restrict__ wk, const float* __restrict__ bk,
                 const float* __restrict__ wv, const float* __restrict__ bv,
                 const float* __restrict__ wo, const float* __restrict__ bo,
                 const float* __restrict__ dww, const float* __restrict__ dwb,
                 const float* __restrict__ lng, const float* __restrict__ lnb,
                 const float* __restrict__ pww, const float* __restrict__ rpe,
                 float* __restrict__ out, int writePR)
{
    extern __shared__ float sm[];
    const int b = blockIdx.x;
    const int tid = threadIdx.x;
    const uint32_t sb = (uint32_t)__cvta_generic_to_shared(sm);

    // async-prefetch q-proj weight pass 0 into buffer 1 (overlaps x staging)
    cp_stage(wq, 0, sb + (uint32_t)(O_WT + WBUF) * 4u, tid);

    // ---- stage x (transpose to [c][p]) and persistent params ----
    const float* xb = x + (size_t)b * (NPOS * CDIM);
    for (int t = tid; t < NPOS * CDIM; t += TPB) {
        int p = t / CDIM;
        int c = t - p * CDIM;
        sm[O_XS + c * RSX + p] = xb[t];
    }
    for (int t = tid; t < 1350; t += TPB) sm[O_RPE + t] = rpe[t];
    for (int t = tid; t < 576; t += TPB) sm[O_DWW + t] = dww[t];
    if (tid < 64) {
        sm[O_DWB + tid] = dwb[tid];
        sm[O_LNG + tid] = lng[tid];
        sm[O_LNB + tid] = lnb[tid];
    }
    if (tid >= 64 && tid < 192) sm[O_PWW + tid - 64] = pww[tid - 64];
    __syncthreads();

    // ---- q = Wq x + bq ----
    gemm_big<true>(wq, bq, O_XS, nullptr, sm, sb, tid);

    // ---- offset network: 48 items (group g, sample s), 3 per warp ----
    const int warp = tid >> 5, lane = tid & 31;
    for (int kk = 0; kk < 3; ++kk) {
        const int item = warp * 3 + kk;
        const int g = item >> 4;
        const int s = item & 15;
        const int si = s >> 2, sj = s & 3;
        const int ch0 = lane, ch1 = lane + 32;
        float v0 = sm[O_DWB + ch0];
        float v1 = sm[O_DWB + ch1];
        const int iy0 = 2 * si - 1, ix0 = 2 * sj - 1;
#pragma unroll
        for (int di = 0; di < 3; ++di) {
            int iy = iy0 + di;
            if (iy < 0 || iy > 7) continue;
#pragma unroll
            for (int dj = 0; dj < 3; ++dj) {
                int ix = ix0 + dj;
                if (ix < 0 || ix > 7) continue;
                float q0 = sm[O_QS + (g * 64 + ch0) * RSQ + iy * 8 + ix];
                float q1 = sm[O_QS + (g * 64 + ch1) * RSQ + iy * 8 + ix];
                v0 += sm[O_DWW + ch0 * 9 + di * 3 + dj] * q0;
                v1 += sm[O_DWW + ch1 * 9 + di * 3 + dj] * q1;
            }
        }
        float ssum = v0 + v1, ssq = v0 * v0 + v1 * v1;
#pragma unroll
        for (int o = 16; o > 0; o >>= 1) {
            ssum += __shfl_xor_sync(0xffffffffu, ssum, o);
            ssq += __shfl_xor_sync(0xffffffffu, ssq, o);
        }
        float mu = ssum * (1.0f / 64.0f);
        float var = ssq * (1.0f / 64.0f) - mu * mu;
        float rstd = rsqrtf(var + 1e-5f);
        v0 = (v0 - mu) * rstd * sm[O_LNG + ch0] + sm[O_LNB + ch0];
        v1 = (v1 - mu) * rstd * sm[O_LNG + ch1] + sm[O_LNB + ch1];
        v0 = 0.5f * v0 * (1.0f + erff(v0 * 0.70710678118654752f));
        v1 = 0.5f * v1 * (1.0f + erff(v1 * 0.70710678118654752f));
        float o0 = sm[O_PWW + ch0] * v0 + sm[O_PWW + ch1] * v1;
        float o1 = sm[O_PWW + 64 + ch0] * v0 + sm[O_PWW + 64 + ch1] * v1;
#pragma unroll
        for (int o = 16; o > 0; o >>= 1) {
            o0 += __shfl_xor_sync(0xffffffffu, o0, o);
            o1 += __shfl_xor_sync(0xffffffffu, o1, o);
        }
        if (lane == 0) {
            float offy = tanhf(o0) * (2.0f / 3.0f);
            float offx = tanhf(o1) * (2.0f / 3.0f);
            float ry = (2 * si - 3) * 0.25f;
            float rx = (2 * sj - 3) * 0.25f;
            float py = offy + ry;
            float px = offx + rx;
            sm[O_POS + item * 2 + 0] = py;
            sm[O_POS + item * 2 + 1] = px;
            float gx = (px + 1.0f) * 3.5f;
            float gy = (py + 1.0f) * 3.5f;
            float x0f = floorf(gx), y0f = floorf(gy);
            int jx0 = (int)x0f, jy0 = (int)y0f;
            float wx1 = gx - x0f, wy1 = gy - y0f;
            float wxs[2] = {1.0f - wx1, wx1};
            float wys[2] = {1.0f - wy1, wy1};
            int* smpI = (int*)sm;
#pragma unroll
            for (int n = 0; n < 4; ++n) {
                int xi = jx0 + (n & 1);
                int yi = jy0 + (n >> 1);
                bool val = (xi >= 0 && xi <= 7 && yi >= 0 && yi <= 7);
                sm[O_SMPW + item * 4 + n] = val ? wxs[n & 1] * wys[n >> 1] : 0.0f;
                smpI[O_SMPI + item * 4 + n] = val ? (yi * 8 + xi) : 0;
            }
            if (writePR) {
                size_t po = ((size_t)b * 48 + item) * 2;
                out[POS_OFF + po + 0] = py;
                out[POS_OFF + po + 1] = px;
                out[REF_OFF + po + 0] = ry;
                out[REF_OFF + po + 1] = rx;
            }
        }
    }
    __syncthreads();

    // ---- bilinear sample x at pos -> samp[c][s] ----
    for (int t = tid; t < CDIM * NS; t += TPB) {
        int c = t >> 4;
        int s = t & 15;
        int item = (c >> 6) * 16 + s;
        const float* wp = &sm[O_SMPW + item * 4];
        const int* ip = ((const int*)sm) + O_SMPI + item * 4;
        const float* row = &sm[O_XS + c * RSX];
        sm[O_SAMP + c * RSS + s] =
            wp[0] * row[ip[0]] + wp[1] * row[ip[1]] + wp[2] * row[ip[2]] + wp[3] * row[ip[3]];
    }
    __syncthreads();

    // ---- k, v projections: weights direct from L2, thread = (co, 8 s-cols) ----
    if (tid < 384) {
        const int co = tid >> 1;
        const int sh = (tid & 1) * 8;
        const float bkc = bk[co], bvc = bv[co];
        float4 ak0 = make_float4(bkc, bkc, bkc, bkc), ak1 = ak0;
        float4 av0 = make_float4(bvc, bvc, bvc, bvc), av1 = av0;
#pragma unroll 4
        for (int k4 = 0; k4 < 48; ++k4) {
            float4 wk4 = __ldg((const float4*)&wk[co * 192 + k4 * 4]);
            float4 wv4 = __ldg((const float4*)&wv[co * 192 + k4 * 4]);
#pragma unroll
            for (int j = 0; j < 4; ++j) {
                float wkj = (j == 0) ? wk4.x : (j == 1) ? wk4.y : (j == 2) ? wk4.z : wk4.w;
                float wvj = (j == 0) ? wv4.x : (j == 1) ? wv4.y : (j == 2) ? wv4.z : wv4.w;
                float4 s0 = *(const float4*)&sm[O_SAMP + (k4 * 4 + j) * RSS + sh];
                float4 s1 = *(const float4*)&sm[O_SAMP + (k4 * 4 + j) * RSS + sh + 4];
                ak0.x += wkj * s0.x; ak0.y += wkj * s0.y; ak0.z += wkj * s0.z; ak0.w += wkj * s0.w;
                ak1.x += wkj * s1.x; ak1.y += wkj * s1.y; ak1.z += wkj * s1.z; ak1.w += wkj * s1.w;
                av0.x += wvj * s0.x; av0.y += wvj * s0.y; av0.z += wvj * s0.z; av0.w += wvj * s0.w;
                av1.x += wvj * s1.x; av1.y += wvj * s1.y; av1.z += wvj * s1.z; av1.w += wvj * s1.w;
            }
        }
        *(float4*)&sm[O_KS + co * RSS + sh] = ak0;
        *(float4*)&sm[O_KS + co * RSS + sh + 4] = ak1;
        *(float4*)&sm[O_VS + co * RSS + sh] = av0;
        *(float4*)&sm[O_VS + co * RSS + sh + 4] = av1;
    }
    __syncthreads();

    // async-prefetch o-proj weight pass 0 into buffer 1 (upper half — does not
    // alias SAMP/KS/VS in buffer 0); attention below hides the latency.
    cp_stage(wo, 0, sb + (uint32_t)(O_WT + WBUF) * 4u, tid);

    // ---- attention: item = (head, query position), 384 items ----
    for (int it = tid; it < NHEAD * NPOS; it += TPB) {
        const int h = it >> 6;
        const int p = it & 63;
        const int g = h >> 1;
        float a[16];
#pragma unroll
        for (int s = 0; s < 16; ++s) a[s] = 0.0f;
#pragma unroll 4
        for (int c = 0; c < 32; ++c) {
            float qv = sm[O_QS + (h * 32 + c) * RSQ + p];
            const float4* kr = (const float4*)&sm[O_KS + (h * 32 + c) * RSS];
            float4 k0 = kr[0], k1 = kr[1], k2 = kr[2], k3 = kr[3];
            a[0] += qv * k0.x; a[1] += qv * k0.y; a[2] += qv * k0.z; a[3] += qv * k0.w;
            a[4] += qv * k1.x; a[5] += qv * k1.y; a[6] += qv * k1.z; a[7] += qv * k1.w;
            a[8] += qv * k2.x; a[9] += qv * k2.y; a[10] += qv * k2.z; a[11] += qv * k2.w;
            a[12] += qv * k3.x; a[13] += qv * k3.y; a[14] += qv * k3.z; a[15] += qv * k3.w;
        }
        const float scale = 0.17677669529663687f;
        float qy = (2 * (p >> 3) - 7) * 0.125f;
        float qx = (2 * (p & 7) - 7) * 0.125f;
        const float* rpeh = &sm[O_RPE + h * 225];
        float mx = -1e30f;
#pragma unroll
        for (int s = 0; s < 16; ++s) {
            float py = sm[O_POS + (g * 16 + s) * 2 + 0];
            float px = sm[O_POS + (g * 16 + s) * 2 + 1];
            float dy = (qy - py) * 0.5f;
            float dx = (qx - px) * 0.5f;
            float gx = (dx + 1.0f) * 7.0f;
            float gy = (dy + 1.0f) * 7.0f;
            float x0f = floorf(gx), y0f = floorf(gy);
            int jx0 = (int)x0f, jy0 = (int)y0f;
            float wx1 = gx - x0f, wy1 = gy - y0f;
            float bias = 0.0f;
            if (jx0 >= 0 && jx0 <= 14 && jy0 >= 0 && jy0 <= 14)
                bias += (1.0f - wx1) * (1.0f - wy1) * rpeh[jy0 * 15 + jx0];
            if (jx0 + 1 >= 0 && jx0 + 1 <= 14 && jy0 >= 0 && jy0 <= 14)
                bias += wx1 * (1.0f - wy1) * rpeh[jy0 * 15 + jx0 + 1];
            if (jx0 >= 0 && jx0 <= 14 && jy0 + 1 >= 0 && jy0 + 1 <= 14)
                bias += (1.0f - wx1) * wy1 * rpeh[(jy0 + 1) * 15 + jx0];
            if (jx0 + 1 >= 0 && jx0 + 1 <= 14 && jy0 + 1 >= 0 && jy0 + 1 <= 14)
                bias += wx1 * wy1 * rpeh[(jy0 + 1) * 15 + jx0 + 1];
            a[s] = a[s] * scale + bias;
            mx = fmaxf(mx, a[s]);
        }
        float ssum = 0.0f;
#pragma unroll
        for (int s = 0; s < 16; ++s) { a[s] = __expf(a[s] - mx); ssum += a[s]; }
        float inv = 1.0f / ssum;
#pragma unroll
        for (int s = 0; s < 16; ++s) a[s] *= inv;
#pragma unroll 4
        for (int cl = 0; cl < 32; ++cl) {
            int c = h * 32 + cl;
            const float4* vr = (const float4*)&sm[O_VS + c * RSS];
            float4 v0 = vr[0], v1 = vr[1], v2 = vr[2], v3 = vr[3];
            float acc = a[0]*v0.x + a[1]*v0.y + a[2]*v0.z + a[3]*v0.w
                      + a[4]*v1.x + a[5]*v1.y + a[6]*v1.z + a[7]*v1.w
                      + a[8]*v2.x + a[9]*v2.y + a[10]*v2.z + a[11]*v2.w
                      + a[12]*v3.x + a[13]*v3.y + a[14]*v3.z + a[15]*v3.w;
            sm[O_XS + c * RSX + p] = acc;
        }
    }
    __syncthreads();

    // ---- y = Wo out + bo (direct to gmem) ----
    gemm_big<false>(wo, bo, O_XS, out + (size_t)b * (CDIM * NPOS), sm, sb, tid);
}

extern "C" void kernel_launch(void* const* d_in, const int* in_sizes, int n_in,
                              void* d_out, int out_size)
{
    (void)in_sizes; (void)n_in;
    const float* x   = (const float*)d_in[0];
    const float* wq  = (const float*)d_in[1];
    const float* bq  = (const float*)d_in[2];
    const float* wk  = (const float*)d_in[3];
    const float* bk  = (const float*)d_in[4];
    const float* wv  = (const float*)d_in[5];
    const float* bv  = (const float*)d_in[6];
    const float* wo  = (const float*)d_in[7];
    const float* bo  = (const float*)d_in[8];
    const float* dww = (const float*)d_in[9];
    const float* dwb = (const float*)d_in[10];
    const float* lng = (const float*)d_in[11];
    const float* lnb = (const float*)d_in[12];
    const float* pww = (const float*)d_in[13];
    const float* rpe = (const float*)d_in[14];
    float* out = (float*)d_out;

    int writePR = (out_size >= (REF_OFF + PR_SIZE)) ? 1 : 0;

    cudaFuncSetAttribute(dat_fused_kernel,
                         cudaFuncAttributeMaxDynamicSharedMemorySize, SMEM_BYTES);
    dat_fused_kernel<<<NBATCH, TPB, SMEM_BYTES>>>(
        x, wq, bq, wk, bk, wv, bv, wo, bo, dww, dwb, lng, lnb, pww, rpe, out, writePR);
}

// round 12
// speedup vs baseline: 1.4503x; 1.0188x over previous
#include <cuda_runtime.h>
#include <cstdint>

#define TPB 512

#define NBATCH 2048
#define CDIM 192
#define NPOS 64
#define NHEAD 6
#define NGRP 3
#define NS 16

#define RSX 68     // row stride for x / attn-out tile [192][64]
#define RSQ 68     // row stride for q tile [192][64]
#define RSW 68     // row stride for weight pass buffer [192 co][64 k] (+4 pad, 16B-aligned)
#define RSS 16     // row stride for samp/k/v tiles [192][16]
#define WBUF 13056 // floats per weight pass buffer (192*68)

// shared-memory layout (float offsets)
#define O_XS    0          // 13056 (x; later attn-out)
#define O_QS    13056      // 13056
#define O_WT    26112      // UNION: 2 weight pass buffers (2*13056)  OR  samp/k/v
#define O_SAMP  (O_WT)             // 3072 (buffer0 region)
#define O_KS    (O_WT + 3072)      // 3072
#define O_VS    (O_WT + 6144)      // 3072
// persistent tail (never aliased by WT)
#define O_RPE   52224      // 1350
#define O_DWW   53574      // 576
#define O_DWB   54150      // 64
#define O_LNG   54214      // 64
#define O_LNB   54278      // 64
#define O_PWW   54342      // 128
#define O_POS   54470      // 96
#define O_SMPW  54566      // 192
#define O_SMPI  54758      // 192 (ints)
#define SMEMF   54950
#define SMEM_BYTES (SMEMF * 4)   // 219800 B

#define Y_SIZE   (NBATCH * CDIM * NPOS)
#define PR_SIZE  (NBATCH * NGRP * NS * 2)
#define POS_OFF  Y_SIZE
#define REF_OFF  (Y_SIZE + PR_SIZE)

typedef unsigned long long ull;

__device__ __forceinline__ ull ffma2(ull a, ull b, ull c) {
    ull d;
    asm("fma.rn.f32x2 %0, %1, %2, %3;" : "=l"(d) : "l"(a), "l"(b), "l"(c));
    return d;
}
__device__ __forceinline__ ull pk2d(float v) {          // (v, v)
    ull r;
    asm("mov.b64 %0, {%1, %1};" : "=l"(r) : "f"(v));
    return r;
}
__device__ __forceinline__ ull pk2(float lo, float hi) {
    ull r;
    asm("mov.b64 %0, {%1, %2};" : "=l"(r) : "f"(lo), "f"(hi));
    return r;
}
__device__ __forceinline__ void unpk2(float& lo, float& hi, ull v) {
    asm("mov.b64 {%0, %1}, %2;" : "=f"(lo), "=f"(hi) : "l"(v));
}

// ---- async-stage one 64-k pass of weights: W[192 co][k0..k0+63] -> smem[co*68 + kc*4] ----
__device__ __forceinline__ void cp_stage(const float* __restrict__ W, int k0,
                                         uint32_t dstBase, int tid)
{
#pragma unroll
    for (int j = 0; j < 6; ++j) {
        int q = tid + j * 512;
        int co = q >> 4;
        int kc = q & 15;
        uint32_t dst = dstBase + (uint32_t)(co * RSW + kc * 4) * 4u;
        const float* src = W + co * 192 + k0 + kc * 4;
        asm volatile("cp.async.cg.shared.global [%0], [%1], 16;" :: "r"(dst), "l"(src));
    }
    asm volatile("cp.async.commit_group;" ::: "memory");
}

// one k-step: dup each of 6 weights to (w,w), 12 packed FFMA2 (24 MACs)
#define KSTEP(CMP, XA, XB) { \
    ull d; \
    d = pk2d(w0.CMP); accA[0] = ffma2(d, XA, accA[0]); accB[0] = ffma2(d, XB, accB[0]); \
    d = pk2d(w1.CMP); accA[1] = ffma2(d, XA, accA[1]); accB[1] = ffma2(d, XB, accB[1]); \
    d = pk2d(w2.CMP); accA[2] = ffma2(d, XA, accA[2]); accB[2] = ffma2(d, XB, accB[2]); \
    d = pk2d(w3.CMP); accA[3] = ffma2(d, XA, accA[3]); accB[3] = ffma2(d, XB, accB[3]); \
    d = pk2d(w4.CMP); accA[4] = ffma2(d, XA, accA[4]); accB[4] = ffma2(d, XB, accB[4]); \
    d = pk2d(w5.CMP); accA[5] = ffma2(d, XA, accA[5]); accB[5] = ffma2(d, XB, accB[5]); \
}

// 192x64 GEMM, K=192: out[co][p] = bias[co] + sum_k W[co][k] * in[k][p]
// 3 K-passes of 64, weights double-buffered via cp.async; packed f32x2 accumulators.
// Thread tile: 6 co x 4 p (as 6 x 2 f32x2 pairs).
template <bool TO_SMEM>
__device__ __forceinline__ void gemm_big(const float* __restrict__ W, const float* __restrict__ bias,
                                         int inOff, float* __restrict__ gout,
                                         float* __restrict__ sm, uint32_t sb, int tid)
{
    const int warp = tid >> 5, lane = tid & 31;
    const int p = ((warp >> 2) * 4 + (lane & 3)) * 4;       // 16 p-quads
    const int col = ((warp & 3) * 8 + (lane >> 2)) * 6;     // 0..186

    ull accA[6], accB[6];
#pragma unroll
    for (int i = 0; i < 6; ++i) {
        float bi = bias[col + i];
        accA[i] = pk2(bi, bi);
        accB[i] = pk2(bi, bi);
    }
    const uint32_t xbase = sb + (uint32_t)(inOff + p) * 4u;

#pragma unroll 1
    for (int pass = 0; pass < 3; ++pass) {
        if (pass < 2) {
            cp_stage(W, (pass + 1) * 64, sb + (uint32_t)(O_WT + (pass & 1) * WBUF) * 4u, tid);
            asm volatile("cp.async.wait_group 1;" ::: "memory");
        } else {
            asm volatile("cp.async.wait_group 0;" ::: "memory");
        }
        __syncthreads();
        const int wb = O_WT + ((pass + 1) & 1) * WBUF;
        const int kb = pass * 64;
#pragma unroll 2
        for (int k4 = 0; k4 < 16; ++k4) {
            float4 w0 = *(const float4*)&sm[wb + (col + 0) * RSW + k4 * 4];
            float4 w1 = *(const float4*)&sm[wb + (col + 1) * RSW + k4 * 4];
            float4 w2 = *(const float4*)&sm[wb + (col + 2) * RSW + k4 * 4];
            float4 w3 = *(const float4*)&sm[wb + (col + 3) * RSW + k4 * 4];
            float4 w4 = *(const float4*)&sm[wb + (col + 4) * RSW + k4 * 4];
            float4 w5 = *(const float4*)&sm[wb + (col + 5) * RSW + k4 * 4];
            ull xA0, xB0, xA1, xB1, xA2, xB2, xA3, xB3;
            {
                uint32_t a0 = xbase + (uint32_t)((kb + k4 * 4 + 0) * RSX) * 4u;
                uint32_t a1 = xbase + (uint32_t)((kb + k4 * 4 + 1) * RSX) * 4u;
                uint32_t a2 = xbase + (uint32_t)((kb + k4 * 4 + 2) * RSX) * 4u;
                uint32_t a3 = xbase + (uint32_t)((kb + k4 * 4 + 3) * RSX) * 4u;
                asm("ld.shared.v2.b64 {%0,%1}, [%2];" : "=l"(xA0), "=l"(xB0) : "r"(a0));
                asm("ld.shared.v2.b64 {%0,%1}, [%2];" : "=l"(xA1), "=l"(xB1) : "r"(a1));
                asm("ld.shared.v2.b64 {%0,%1}, [%2];" : "=l"(xA2), "=l"(xB2) : "r"(a2));
                asm("ld.shared.v2.b64 {%0,%1}, [%2];" : "=l"(xA3), "=l"(xB3) : "r"(a3));
            }
            KSTEP(x, xA0, xB0);
            KSTEP(y, xA1, xB1);
            KSTEP(z, xA2, xB2);
            KSTEP(w, xA3, xB3);
        }
        __syncthreads();   // buffer free for the next pass's cp.async
    }

#pragma unroll
    for (int i = 0; i < 6; ++i) {
        float4 v;
        unpk2(v.x, v.y, accA[i]);
        unpk2(v.z, v.w, accB[i]);
        if (TO_SMEM) *(float4*)&sm[O_QS + (col + i) * RSQ + p] = v;
        else         *(float4*)&gout[(col + i) * 64 + p] = v;
    }
    __syncthreads();
}

__global__ void __launch_bounds__(TPB, 1)
dat_fused_kernel(const float* __restrict__ x,
                 const float* __restrict__ wq, const float* __restrict__ bq,
                 const float* __restrict__ wk, const float* __restrict__ bk,
                 const float* __restrict__ wv, const float* __restrict__ bv,
                 const float* __restrict__ wo, const float* __restrict__ bo,
                 const float* __restrict__ dww, const float* __restrict__ dwb,
                 const float* __restrict__ lng, const float* __restrict__ lnb,
                 const float* __restrict__ pww, const float* __restrict__ rpe,
                 float* __restrict__ out, int writePR)
{
    extern __shared__ float sm[];
    const int b = blockIdx.x;
    const int tid = threadIdx.x;
    const uint32_t sb = (uint32_t)__cvta_generic_to_shared(sm);

    // async-prefetch q-proj weight pass 0 into buffer 1 (overlaps x staging)
    cp_stage(wq, 0, sb + (uint32_t)(O_WT + WBUF) * 4u, tid);

    // ---- stage x (transpose to [c][p]) and persistent params ----
    const float* xb = x + (size_t)b * (NPOS * CDIM);
    for (int t = tid; t < NPOS * CDIM; t += TPB) {
        int p = t / CDIM;
        int c = t - p * CDIM;
        sm[O_XS + c * RSX + p] = xb[t];
    }
    for (int t = tid; t < 1350; t += TPB) sm[O_RPE + t] = rpe[t];
    for (int t = tid; t < 576; t += TPB) sm[O_DWW + t] = dww[t];
    if (tid < 64) {
        sm[O_DWB + tid] = dwb[tid];
        sm[O_LNG + tid] = lng[tid];
        sm[O_LNB + tid] = lnb[tid];
    }
    if (tid >= 64 && tid < 192) sm[O_PWW + tid - 64] = pww[tid - 64];
    __syncthreads();

    // ---- q = Wq x + bq ----
    gemm_big<true>(wq, bq, O_XS, nullptr, sm, sb, tid);

    // ---- offset network: 48 items (group g, sample s), 3 per warp ----
    const int warp = tid >> 5, lane = tid & 31;
    for (int kk = 0; kk < 3; ++kk) {
        const int item = warp * 3 + kk;
        const int g = item >> 4;
        const int s = item & 15;
        const int si = s >> 2, sj = s & 3;
        const int ch0 = lane, ch1 = lane + 32;
        float v0 = sm[O_DWB + ch0];
        float v1 = sm[O_DWB + ch1];
        const int iy0 = 2 * si - 1, ix0 = 2 * sj - 1;
#pragma unroll
        for (int di = 0; di < 3; ++di) {
            int iy = iy0 + di;
            if (iy < 0 || iy > 7) continue;
#pragma unroll
            for (int dj = 0; dj < 3; ++dj) {
                int ix = ix0 + dj;
                if (ix < 0 || ix > 7) continue;
                float q0 = sm[O_QS + (g * 64 + ch0) * RSQ + iy * 8 + ix];
                float q1 = sm[O_QS + (g * 64 + ch1) * RSQ + iy * 8 + ix];
                v0 += sm[O_DWW + ch0 * 9 + di * 3 + dj] * q0;
                v1 += sm[O_DWW + ch1 * 9 + di * 3 + dj] * q1;
            }
        }
        float ssum = v0 + v1, ssq = v0 * v0 + v1 * v1;
#pragma unroll
        for (int o = 16; o > 0; o >>= 1) {
            ssum += __shfl_xor_sync(0xffffffffu, ssum, o);
            ssq += __shfl_xor_sync(0xffffffffu, ssq, o);
        }
        float mu = ssum * (1.0f / 64.0f);
        float var = ssq * (1.0f / 64.0f) - mu * mu;
        float rstd = rsqrtf(var + 1e-5f);
        v0 = (v0 - mu) * rstd * sm[O_LNG + ch0] + sm[O_LNB + ch0];
        v1 = (v1 - mu) * rstd * sm[O_LNG + ch1] + sm[O_LNB + ch1];
        v0 = 0.5f * v0 * (1.0f + erff(v0 * 0.70710678118654752f));
        v1 = 0.5f * v1 * (1.0f + erff(v1 * 0.70710678118654752f));
        float o0 = sm[O_PWW + ch0] * v0 + sm[O_PWW + ch1] * v1;
        float o1 = sm[O_PWW + 64 + ch0] * v0 + sm[O_PWW + 64 + ch1] * v1;
#pragma unroll
        for (int o = 16; o > 0; o >>= 1) {
            o0 += __shfl_xor_sync(0xffffffffu, o0, o);
            o1 += __shfl_xor_sync(0xffffffffu, o1, o);
        }
        if (lane == 0) {
            float offy = tanhf(o0) * (2.0f / 3.0f);
            float offx = tanhf(o1) * (2.0f / 3.0f);
            float ry = (2 * si - 3) * 0.25f;
            float rx = (2 * sj - 3) * 0.25f;
            float py = offy + ry;
            float px = offx + rx;
            sm[O_POS + item * 2 + 0] = py;
            sm[O_POS + item * 2 + 1] = px;
            float gx = (px + 1.0f) * 3.5f;
            float gy = (py + 1.0f) * 3.5f;
            float x0f = floorf(gx), y0f = floorf(gy);
            int jx0 = (int)x0f, jy0 = (int)y0f;
            float wx1 = gx - x0f, wy1 = gy - y0f;
            float wxs[2] = {1.0f - wx1, wx1};
            float wys[2] = {1.0f - wy1, wy1};
            int* smpI = (int*)sm;
#pragma unroll
            for (int n = 0; n < 4; ++n) {
                int xi = jx0 + (n & 1);
                int yi = jy0 + (n >> 1);
                bool val = (xi >= 0 && xi <= 7 && yi >= 0 && yi <= 7);
                sm[O_SMPW + item * 4 + n] = val ? wxs[n & 1] * wys[n >> 1] : 0.0f;
                smpI[O_SMPI + item * 4 + n] = val ? (yi * 8 + xi) : 0;
            }
            if (writePR) {
                size_t po = ((size_t)b * 48 + item) * 2;
                out[POS_OFF + po + 0] = py;
                out[POS_OFF + po + 1] = px;
                out[REF_OFF + po + 0] = ry;
                out[REF_OFF + po + 1] = rx;
            }
        }
    }
    __syncthreads();

    // ---- bilinear sample x at pos -> samp[c][s] ----
    for (int t = tid; t < CDIM * NS; t += TPB) {
        int c = t >> 4;
        int s = t & 15;
        int item = (c >> 6) * 16 + s;
        const float* wp = &sm[O_SMPW + item * 4];
        const int* ip = ((const int*)sm) + O_SMPI + item * 4;
        const float* row = &sm[O_XS + c * RSX];
        sm[O_SAMP + c * RSS + s] =
            wp[0] * row[ip[0]] + wp[1] * row[ip[1]] + wp[2] * row[ip[2]] + wp[3] * row[ip[3]];
    }
    __syncthreads();

    // ---- k, v projections: weights direct from L2, thread = (co, 8 s-cols) ----
    if (tid < 384) {
        const int co = tid >> 1;
        const int sh = (tid & 1) * 8;
        const float bkc = bk[co], bvc = bv[co];
        float4 ak0 = make_float4(bkc, bkc, bkc, bkc), ak1 = ak0;
        float4 av0 = make_float4(bvc, bvc, bvc, bvc), av1 = av0;
#pragma unroll 4
        for (int k4 = 0; k4 < 48; ++k4) {
            float4 wk4 = __ldg((const float4*)&wk[co * 192 + k4 * 4]);
            float4 wv4 = __ldg((const float4*)&wv[co * 192 + k4 * 4]);
#pragma unroll
            for (int j = 0; j < 4; ++j) {
                float wkj = (j == 0) ? wk4.x : (j == 1) ? wk4.y : (j == 2) ? wk4.z : wk4.w;
                float wvj = (j == 0) ? wv4.x : (j == 1) ? wv4.y : (j == 2) ? wv4.z : wv4.w;
                float4 s0 = *(const float4*)&sm[O_SAMP + (k4 * 4 + j) * RSS + sh];
                float4 s1 = *(const float4*)&sm[O_SAMP + (k4 * 4 + j) * RSS + sh + 4];
                ak0.x += wkj * s0.x; ak0.y += wkj * s0.y; ak0.z += wkj * s0.z; ak0.w += wkj * s0.w;
                ak1.x += wkj * s1.x; ak1.y += wkj * s1.y; ak1.z += wkj * s1.z; ak1.w += wkj * s1.w;
                av0.x += wvj * s0.x; av0.y += wvj * s0.y; av0.z += wvj * s0.z; av0.w += wvj * s0.w;
                av1.x += wvj * s1.x; av1.y += wvj * s1.y; av1.z += wvj * s1.z; av1.w += wvj * s1.w;
            }
        }
        *(float4*)&sm[O_KS + co * RSS + sh] = ak0;
        *(float4*)&sm[O_KS + co * RSS + sh + 4] = ak1;
        *(float4*)&sm[O_VS + co * RSS + sh] = av0;
        *(float4*)&sm[O_VS + co * RSS + sh + 4] = av1;
    }
    __syncthreads();

    // async-prefetch o-proj weight pass 0 into buffer 1 (upper half — does not
    // alias SAMP/KS/VS in buffer 0); attention below hides the latency.
    cp_stage(wo, 0, sb + (uint32_t)(O_WT + WBUF) * 4u, tid);

    // ---- attention: item = (head, query position), 384 items ----
    for (int it = tid; it < NHEAD * NPOS; it += TPB) {
        const int h = it >> 6;
        const int p = it & 63;
        const int g = h >> 1;
        float a[16];
#pragma unroll
        for (int s = 0; s < 16; ++s) a[s] = 0.0f;
#pragma unroll 4
        for (int c = 0; c < 32; ++c) {
            float qv = sm[O_QS + (h * 32 + c) * RSQ + p];
            const float4* kr = (const float4*)&sm[O_KS + (h * 32 + c) * RSS];
            float4 k0 = kr[0], k1 = kr[1], k2 = kr[2], k3 = kr[3];
            a[0] += qv * k0.x; a[1] += qv * k0.y; a[2] += qv * k0.z; a[3] += qv * k0.w;
            a[4] += qv * k1.x; a[5] += qv * k1.y; a[6] += qv * k1.z; a[7] += qv * k1.w;
            a[8] += qv * k2.x; a[9] += qv * k2.y; a[10] += qv * k2.z; a[11] += qv * k2.w;
            a[12] += qv * k3.x; a[13] += qv * k3.y; a[14] += qv * k3.z; a[15] += qv * k3.w;
        }
        const float scale = 0.17677669529663687f;
        float qy = (2 * (p >> 3) - 7) * 0.125f;
        float qx = (2 * (p & 7) - 7) * 0.125f;
        const float* rpeh = &sm[O_RPE + h * 225];
        float mx = -1e30f;
#pragma unroll
        for (int s = 0; s < 16; ++s) {
            float py = sm[O_POS + (g * 16 + s) * 2 + 0];
            float px = sm[O_POS + (g * 16 + s) * 2 + 1];
            float dy = (qy - py) * 0.5f;
            float dx = (qx - px) * 0.5f;
            float gx = (dx + 1.0f) * 7.0f;
            float gy = (dy + 1.0f) * 7.0f;
            float x0f = floorf(gx), y0f = floorf(gy);
            int jx0 = (int)x0f, jy0 = (int)y0f;
            float wx1 = gx - x0f, wy1 = gy - y0f;
            float bias = 0.0f;
            if (jx0 >= 0 && jx0 <= 14 && jy0 >= 0 && jy0 <= 14)
                bias += (1.0f - wx1) * (1.0f - wy1) * rpeh[jy0 * 15 + jx0];
            if (jx0 + 1 >= 0 && jx0 + 1 <= 14 && jy0 >= 0 && jy0 <= 14)
                bias += wx1 * (1.0f - wy1) * rpeh[jy0 * 15 + jx0 + 1];
            if (jx0 >= 0 && jx0 <= 14 && jy0 + 1 >= 0 && jy0 + 1 <= 14)
                bias += (1.0f - wx1) * wy1 * rpeh[(jy0 + 1) * 15 + jx0];
            if (jx0 + 1 >= 0 && jx0 + 1 <= 14 && jy0 + 1 >= 0 && jy0 + 1 <= 14)
                bias += wx1 * wy1 * rpeh[(jy0 + 1) * 15 + jx0 + 1];
            a[s] = a[s] * scale + bias;
            mx = fmaxf(mx, a[s]);
        }
        float ssum = 0.0f;
#pragma unroll
        for (int s = 0; s < 16; ++s) { a[s] = __expf(a[s] - mx); ssum += a[s]; }
        float inv = 1.0f / ssum;
#pragma unroll
        for (int s = 0; s < 16; ++s) a[s] *= inv;
#pragma unroll 4
        for (int cl = 0; cl < 32; ++cl) {
            int c = h * 32 + cl;
            const float4* vr = (const float4*)&sm[O_VS + c * RSS];
            float4 v0 = vr[0], v1 = vr[1], v2 = vr[2], v3 = vr[3];
            float acc = a[0]*v0.x + a[1]*v0.y + a[2]*v0.z + a[3]*v0.w
                      + a[4]*v1.x + a[5]*v1.y + a[6]*v1.z + a[7]*v1.w
                      + a[8]*v2.x + a[9]*v2.y + a[10]*v2.z + a[11]*v2.w
                      + a[12]*v3.x + a[13]*v3.y + a[14]*v3.z + a[15]*v3.w;
            sm[O_XS + c * RSX + p] = acc;
        }
    }
    __syncthreads();

    // ---- y = Wo out + bo (direct to gmem) ----
    gemm_big<false>(wo, bo, O_XS, out + (size_t)b * (CDIM * NPOS), sm, sb, tid);
}

extern "C" void kernel_launch(void* const* d_in, const int* in_sizes, int n_in,
                              void* d_out, int out_size)
{
    (void)in_sizes; (void)n_in;
    const float* x   = (const float*)d_in[0];
    const float* wq  = (const float*)d_in[1];
    const float* bq  = (const float*)d_in[2];
    const float* wk  = (const float*)d_in[3];
    const float* bk  = (const float*)d_in[4];
    const float* wv  = (const float*)d_in[5];
    const float* bv  = (const float*)d_in[6];
    const float* wo  = (const float*)d_in[7];
    const float* bo  = (const float*)d_in[8];
    const float* dww = (const float*)d_in[9];
    const float* dwb = (const float*)d_in[10];
    const float* lng = (const float*)d_in[11];
    const float* lnb = (const float*)d_in[12];
    const float* pww = (const float*)d_in[13];
    const float* rpe = (const float*)d_in[14];
    float* out = (float*)d_out;

    int writePR = (out_size >= (REF_OFF + PR_SIZE)) ? 1 : 0;

    cudaFuncSetAttribute(dat_fused_kernel,
                         cudaFuncAttributeMaxDynamicSharedMemorySize, SMEM_BYTES);
    dat_fused_kernel<<<NBATCH, TPB, SMEM_BYTES>>>(
        x, wq, bq, wk, bk, wv, bv, wo, bo, dww, dwb, lng, lnb, pww, rpe, out, writePR);
}